// round 7
// baseline (speedup 1.0000x reference)
#include <cuda_runtime.h>

#define NW      10
#define DIM     1024
#define THREADS 128

typedef unsigned long long ull;

// ---------- packed f32x2 helpers ----------
__device__ __forceinline__ ull pk(float lo, float hi) {
    ull r;
    asm("mov.b64 %0, {%1, %2};" : "=l"(r)
        : "r"(__float_as_uint(lo)), "r"(__float_as_uint(hi)));
    return r;
}
__device__ __forceinline__ void upk(ull v, float& lo, float& hi) {
    unsigned a, b;
    asm("mov.b64 {%0, %1}, %2;" : "=r"(a), "=r"(b) : "l"(v));
    lo = __uint_as_float(a); hi = __uint_as_float(b);
}
__device__ __forceinline__ ull swp(ull v) {
    float lo, hi; upk(v, lo, hi); return pk(hi, lo);
}
__device__ __forceinline__ ull fma2(ull a, ull b, ull c) {
    ull d;
    asm("fma.rn.f32x2 %0, %1, %2, %3;" : "=l"(d) : "l"(a), "l"(b), "l"(c));
    return d;
}
__device__ __forceinline__ ull mul2(ull a, ull b) {
    ull d;
    asm("mul.rn.f32x2 %0, %1, %2;" : "=l"(d) : "l"(a), "l"(b));
    return d;
}
__device__ __forceinline__ ull shflidx64(ull v, int sl) {
    float lo, hi; upk(v, lo, hi);
    lo = __shfl_sync(0xffffffffu, lo, sl);
    hi = __shfl_sync(0xffffffffu, hi, sl);
    return pk(lo, hi);
}

// ---------- gate coefficients ----------
// Per complex gate j (16 floats): [ar,ar, -ai,ai, br,br, -bi,bi, cr,cr, -ci,ci, dr,dr, -di,di]
// Per real gate j (8 floats):     [c,c, s,s, -s,-s, 0,0]
__device__ __align__(16) float d_g1f[NW * 16];
__device__ __align__(16) float d_g2f[NW * 8];
__constant__ __align__(16) float c_g1f[NW * 16];
__constant__ __align__(16) float c_g2f[NW * 8];

__global__ void qsa_prep(const float* __restrict__ rx0,
                         const float* __restrict__ ry0,
                         const float* __restrict__ ry1) {
    int j = threadIdx.x;
    if (j < NW) {
        float cx, sx, cy, sy, cz, sz;
        sincosf(0.5f * rx0[j], &sx, &cx);
        sincosf(0.5f * ry0[j], &sy, &cy);
        sincosf(0.5f * ry1[j], &sz, &cz);
        // G = RY(ry0)@RX(rx0): a = cx*cy + i sx*sy ; b = -sy*cx - i sx*cy ;
        //                      c = sy*cx - i sx*cy ; d = cx*cy - i sx*sy
        float ar =  cx * cy, ai =  sx * sy;
        float br = -sy * cx, bi = -sx * cy;
        float cr =  sy * cx, ci = -sx * cy;
        float dr =  cx * cy, di = -sx * sy;
        float* g = d_g1f + j * 16;
        g[0]=ar;  g[1]=ar;   g[2]=-ai; g[3]=ai;
        g[4]=br;  g[5]=br;   g[6]=-bi; g[7]=bi;
        g[8]=cr;  g[9]=cr;   g[10]=-ci;g[11]=ci;
        g[12]=dr; g[13]=dr;  g[14]=-di;g[15]=di;
        float* h = d_g2f + j * 8;
        h[0]=cz; h[1]=cz; h[2]=sz; h[3]=sz; h[4]=-sz; h[5]=-sz; h[6]=0.f; h[7]=0.f;
    }
}

// ---------- gates on 32-amplitude register state ----------
// Complex 2x2 on register bit kb (packed).
__device__ __forceinline__ void cgate_reg32(ull* r, const int j, const int kb) {
    const ull* g = (const ull*)c_g1f + j * 8;
    const ull a2 = g[0], ai2 = g[1], b2 = g[2], bi2 = g[3];
    const ull c2 = g[4], ci2 = g[5], d2 = g[6], di2 = g[7];
#pragma unroll
    for (int m = 0; m < 32; m++) {
        if ((m >> kb) & 1) continue;
        const int m1 = m | (1 << kb);
        ull u = r[m], v = r[m1];
        ull us = swp(u), vs = swp(v);
        r[m]  = fma2(a2, u, fma2(ai2, us, fma2(b2, v, mul2(bi2, vs))));
        r[m1] = fma2(c2, u, fma2(ci2, us, fma2(d2, v, mul2(di2, vs))));
    }
}

// Complex 2x2 on lane bit lb (scalar math; 2 SHFL + 8 FFMA per amplitude).
__device__ __forceinline__ void cgate_shfl32(ull* r, const int j,
                                             const int lb, const int lane) {
    const float* f = c_g1f + j * 16;
    const bool hi = (lane >> lb) & 1;
    const float pr = hi ? f[12] : f[0];
    const float pi = hi ? f[15] : f[3];
    const float qr = hi ? f[8]  : f[4];
    const float qi = hi ? f[11] : f[7];
#pragma unroll
    for (int m = 0; m < 32; m++) {
        float ux, uy; upk(r[m], ux, uy);
        float vx = __shfl_xor_sync(0xffffffffu, ux, 1 << lb);
        float vy = __shfl_xor_sync(0xffffffffu, uy, 1 << lb);
        float ox = pr * ux - pi * uy + qr * vx - qi * vy;
        float oy = pr * uy + pi * ux + qr * vy + qi * vx;
        r[m] = pk(ox, oy);
    }
}

// Real RY on register bit kb (packed).
__device__ __forceinline__ void rgate_reg32(ull* r, const int j, const int kb) {
    const ull* g = (const ull*)c_g2f + j * 4;
    const ull c2 = g[0], s2 = g[1], ns2 = g[2];
#pragma unroll
    for (int m = 0; m < 32; m++) {
        if ((m >> kb) & 1) continue;
        const int m1 = m | (1 << kb);
        ull u = r[m], v = r[m1];
        r[m]  = fma2(c2, u, mul2(ns2, v));
        r[m1] = fma2(c2, v, mul2(s2, u));
    }
}

// Real RY on lane bit lb (scalar).
__device__ __forceinline__ void rgate_shfl32(ull* r, const int j,
                                             const int lb, const int lane) {
    const float* f = c_g2f + j * 8;
    const bool hi = (lane >> lb) & 1;
    const float c = f[0];
    const float q = hi ? f[2] : f[4];
#pragma unroll
    for (int m = 0; m < 32; m++) {
        float ux, uy; upk(r[m], ux, uy);
        float vx = __shfl_xor_sync(0xffffffffu, ux, 1 << lb);
        float vy = __shfl_xor_sync(0xffffffffu, uy, 1 << lb);
        r[m] = pk(c * ux + q * vx, c * uy + q * vy);
    }
}

__global__ __launch_bounds__(THREADS, 4)
void qsa_main(const float* __restrict__ x, float* __restrict__ out,
              const int nrows) {
    const int lane  = threadIdx.x & 31;
    const int gw    = blockIdx.x * (THREADS / 32) + (threadIdx.x >> 5);
    const int nwarp = gridDim.x * (THREADS / 32);

    for (int row = gw; row < nrows; row += nwarp) {
        // ---- Load: amplitude i: lane = bits 0-4, reg R = bits 5-9 ----
        ull r[32];
        float ss = 0.f;
        const float* xr = x + (size_t)row * DIM;
#pragma unroll
        for (int R = 0; R < 32; R++) {
            float v = __ldg(xr + (R << 5) + lane);
            r[R] = pk(v, 0.f);
            ss += v * v;
        }
#pragma unroll
        for (int o = 16; o; o >>= 1) ss += __shfl_xor_sync(0xffffffffu, ss, o);

        // ======== Layer 1: qubit q <-> global bit 9-q ========
        cgate_reg32(r, 0, 4);          // q0 (bit9 = reg bit4)
        cgate_reg32(r, 1, 3);          // q1
        cgate_reg32(r, 2, 2);          // q2
        cgate_reg32(r, 3, 1);          // q3
        cgate_reg32(r, 4, 0);          // q4 (bit5 = reg bit0)
        cgate_shfl32(r, 5, 4, lane);   // q5 (bit4 = lane bit4)
        cgate_shfl32(r, 6, 3, lane);   // q6
        cgate_shfl32(r, 7, 2, lane);   // q7
        cgate_shfl32(r, 8, 1, lane);   // q8
        cgate_shfl32(r, 9, 0, lane);   // q9 (bit0 = lane bit0)

        // ======== CNOT ring permutation ========
        // dst = phi(sigma(i)): sigma = suffix-XOR (all bits), phi: bit9 ^= bit0.
        // sigma gather: new[R] = shfl(old[R ^ (R>>1)], srclane), srclane uniform
        // per R: sl0 for even R, sl0^16 for odd R. phi is NOT applied as data
        // movement; instead slot (lane L, reg R) is tagged as holding the element
        // with true bit9 = R_4 ^ L_0 (absorbed into the q0/q9 gates + reduction).
        {
            const int sl0 = lane ^ (lane >> 1);
            const int sl1 = sl0 ^ 16;
            r[0] = shflidx64(r[0], sl0);
            r[1] = shflidx64(r[1], sl1);
            { ull t = r[2];
              r[2] = shflidx64(r[3], sl0);  r[3] = shflidx64(t, sl1); }
            { ull t = r[4];                                   // (4 6 5 7)
              r[4] = shflidx64(r[6], sl0);  r[6] = shflidx64(r[5], sl0);
              r[5] = shflidx64(r[7], sl1);  r[7] = shflidx64(t, sl1); }
            { ull t = r[8];                                   // (8 12 10 15)
              r[8]  = shflidx64(r[12], sl0); r[12] = shflidx64(r[10], sl0);
              r[10] = shflidx64(r[15], sl0); r[15] = shflidx64(t, sl1); }
            { ull t = r[9];                                   // (9 13 11 14)
              r[9]  = shflidx64(r[13], sl1); r[13] = shflidx64(r[11], sl1);
              r[11] = shflidx64(r[14], sl1); r[14] = shflidx64(t, sl0); }
            { ull t = r[16];                    // (16 24 20 30 17 25 21 31)
              r[16] = shflidx64(r[24], sl0); r[24] = shflidx64(r[20], sl0);
              r[20] = shflidx64(r[30], sl0); r[30] = shflidx64(r[17], sl0);
              r[17] = shflidx64(r[25], sl1); r[25] = shflidx64(r[21], sl1);
              r[21] = shflidx64(r[31], sl1); r[31] = shflidx64(t, sl1); }
            { ull t = r[18];                    // (18 27 22 29 19 26 23 28)
              r[18] = shflidx64(r[27], sl0); r[27] = shflidx64(r[22], sl1);
              r[22] = shflidx64(r[29], sl0); r[29] = shflidx64(r[19], sl1);
              r[19] = shflidx64(r[26], sl1); r[26] = shflidx64(r[23], sl0);
              r[23] = shflidx64(r[28], sl1); r[28] = shflidx64(t, sl0); }
        }

        // ======== Layer 2 (real RY) ========
        // q0: reg bit4, but odd lanes hold bit9-flipped elements -> sign-swapped s.
        {
            const ull* g = (const ull*)c_g2f;   // gate 0: {c2, s2, ns2, pad}
            const ull c2  = g[0];
            const bool od = lane & 1;
            const ull qv  = od ? g[1] : g[2];   // coeff on partner for A'
            const ull nqv = od ? g[2] : g[1];   // coeff on A for B'
#pragma unroll
            for (int m = 0; m < 16; m++) {
                ull A = r[m], B = r[m + 16];
                r[m]      = fma2(c2, A, mul2(qv,  B));
                r[m + 16] = fma2(c2, B, mul2(nqv, A));
            }
        }
        rgate_reg32(r, 1, 3);           // q1
        rgate_reg32(r, 2, 2);           // q2
        rgate_reg32(r, 3, 1);           // q3
        rgate_reg32(r, 4, 0);           // q4
        rgate_shfl32(r, 5, 4, lane);    // q5
        rgate_shfl32(r, 6, 3, lane);    // q6
        rgate_shfl32(r, 7, 2, lane);    // q7
        rgate_shfl32(r, 8, 1, lane);    // q8
        // q9: lane bit0, partner's element lives at reg R^16 (flip tag differs).
        {
            const float* f = c_g2f + 9 * 8;
            const float c = f[0];
            const float q = (lane & 1) ? f[2] : f[4];
#pragma unroll
            for (int m = 0; m < 16; m++) {
                float ax, ay, bx, by;
                upk(r[m], ax, ay); upk(r[m + 16], bx, by);
                float eax = __shfl_xor_sync(0xffffffffu, bx, 1);
                float eay = __shfl_xor_sync(0xffffffffu, by, 1);
                float ebx = __shfl_xor_sync(0xffffffffu, ax, 1);
                float eby = __shfl_xor_sync(0xffffffffu, ay, 1);
                r[m]      = pk(c * ax + q * eax, c * ay + q * eay);
                r[m + 16] = pk(c * bx + q * ebx, c * by + q * eby);
            }
        }

        // ======== <Z_j> reduction ========
        // slot (L,R): bits0-4 = L, bits5-8 = R_0..3, bit9 = R_4 ^ L_0.
        float tot = 0.f, s0 = 0.f, s1 = 0.f, s2 = 0.f, s3 = 0.f, s4 = 0.f;
#pragma unroll
        for (int R = 0; R < 32; R++) {
            float px, py; upk(r[R], px, py);
            float p = px * px + py * py;
            tot += p;
            s0 += (R & 1)  ? -p : p;   // bit5 -> q4
            s1 += (R & 2)  ? -p : p;   // bit6 -> q3
            s2 += (R & 4)  ? -p : p;   // bit7 -> q2
            s3 += (R & 8)  ? -p : p;   // bit8 -> q1
            s4 += (R & 16) ? -p : p;   // bit9 partial (q0)
        }
        float e0 = (lane & 1) ? -s4 : s4;   // apply L_0 part of bit9 sign
        // plain lane reductions for e0, s0..s3
#pragma unroll
        for (int o = 16; o; o >>= 1) {
            e0 += __shfl_xor_sync(0xffffffffu, e0, o);
            s0 += __shfl_xor_sync(0xffffffffu, s0, o);
            s1 += __shfl_xor_sync(0xffffffffu, s1, o);
            s2 += __shfl_xor_sync(0xffffffffu, s2, o);
            s3 += __shfl_xor_sync(0xffffffffu, s3, o);
        }
        // spawning tree on tot over lane bits: d4 -> q5 ... d0 -> q9
        float s = tot, d4, d3, d2v, d1, d0;
        {
            float n = __shfl_xor_sync(0xffffffffu, s, 16);
            d4 = (lane & 16) ? n - s : s - n; s += n;
        }
        {
            float n = __shfl_xor_sync(0xffffffffu, s, 8);
            d3 = (lane & 8) ? n - s : s - n; s += n;
            d4 += __shfl_xor_sync(0xffffffffu, d4, 8);
        }
        {
            float n = __shfl_xor_sync(0xffffffffu, s, 4);
            d2v = (lane & 4) ? n - s : s - n; s += n;
            d4 += __shfl_xor_sync(0xffffffffu, d4, 4);
            d3 += __shfl_xor_sync(0xffffffffu, d3, 4);
        }
        {
            float n = __shfl_xor_sync(0xffffffffu, s, 2);
            d1 = (lane & 2) ? n - s : s - n; s += n;
            d4 += __shfl_xor_sync(0xffffffffu, d4, 2);
            d3 += __shfl_xor_sync(0xffffffffu, d3, 2);
            d2v += __shfl_xor_sync(0xffffffffu, d2v, 2);
        }
        {
            float n = __shfl_xor_sync(0xffffffffu, s, 1);
            d0 = (lane & 1) ? n - s : s - n;
            d4 += __shfl_xor_sync(0xffffffffu, d4, 1);
            d3 += __shfl_xor_sync(0xffffffffu, d3, 1);
            d2v += __shfl_xor_sync(0xffffffffu, d2v, 1);
            d1 += __shfl_xor_sync(0xffffffffu, d1, 1);
        }

        const float inv = 1.f / fmaxf(ss, 1e-24f);   // == 1/max(norm,1e-12)^2
        float* orow = out + (size_t)row * NW;
        if (lane == 0) orow[0] = e0  * inv;   // q0
        if (lane == 1) orow[1] = s3  * inv;   // q1 (bit8)
        if (lane == 2) orow[2] = s2  * inv;   // q2
        if (lane == 3) orow[3] = s1  * inv;   // q3
        if (lane == 4) orow[4] = s0  * inv;   // q4
        if (lane == 5) orow[5] = d4  * inv;   // q5
        if (lane == 6) orow[6] = d3  * inv;   // q6
        if (lane == 7) orow[7] = d2v * inv;   // q7
        if (lane == 8) orow[8] = d1  * inv;   // q8
        if (lane == 9) orow[9] = d0  * inv;   // q9
    }
}

extern "C" void kernel_launch(void* const* d_in, const int* in_sizes, int n_in,
                              void* d_out, int out_size) {
    const float* x   = (const float*)d_in[0];
    const float* rx0 = (const float*)d_in[1];
    const float* ry0 = (const float*)d_in[2];
    const float* ry1 = (const float*)d_in[3];
    float* out = (float*)d_out;

    int nrows = in_sizes[0] / DIM;  // 4096

    qsa_prep<<<1, 32>>>(rx0, ry0, ry1);

    void *p1 = nullptr, *p2 = nullptr;
    cudaGetSymbolAddress(&p1, d_g1f);
    cudaGetSymbolAddress(&p2, d_g2f);
    cudaMemcpyToSymbolAsync(c_g1f, p1, sizeof(float) * NW * 16, 0,
                            cudaMemcpyDeviceToDevice, 0);
    cudaMemcpyToSymbolAsync(c_g2f, p2, sizeof(float) * NW * 8, 0,
                            cudaMemcpyDeviceToDevice, 0);

    // One warp per row, 2 rows per warp: 512 CTAs x 4 warps x 2 = 4096 rows.
    int grid = (nrows + 7) / 8;
    if (grid > 512) grid = 512;
    qsa_main<<<grid, THREADS>>>(x, out, nrows);
}

// round 8
// speedup vs baseline: 1.1569x; 1.1569x over previous
#include <cuda_runtime.h>

#define NW      10
#define DIM     1024
#define THREADS 128

typedef unsigned long long ull;

// ---------- packed f32x2 helpers ----------
__device__ __forceinline__ ull pk(float lo, float hi) {
    ull r;
    asm("mov.b64 %0, {%1, %2};" : "=l"(r)
        : "r"(__float_as_uint(lo)), "r"(__float_as_uint(hi)));
    return r;
}
__device__ __forceinline__ void upk(ull v, float& lo, float& hi) {
    unsigned a, b;
    asm("mov.b64 {%0, %1}, %2;" : "=r"(a), "=r"(b) : "l"(v));
    lo = __uint_as_float(a); hi = __uint_as_float(b);
}
__device__ __forceinline__ ull swp(ull v) {
    float lo, hi; upk(v, lo, hi); return pk(hi, lo);
}
__device__ __forceinline__ ull fma2(ull a, ull b, ull c) {
    ull d;
    asm("fma.rn.f32x2 %0, %1, %2, %3;" : "=l"(d) : "l"(a), "l"(b), "l"(c));
    return d;
}
__device__ __forceinline__ ull mul2(ull a, ull b) {
    ull d;
    asm("mul.rn.f32x2 %0, %1, %2;" : "=l"(d) : "l"(a), "l"(b));
    return d;
}

// ---------- gate coefficients (one merged array -> one copy node) ----------
// [j*8 .. j*8+7]        : complex fused RY*RX gate j: a2 ai2 b2 bi2 c2 ci2 d2 di2
// [80 + j*4 .. +2]      : real RY gate j: c2 s2 ns2 (pad)
#define G2OFF (NW * 8)
__device__    ull d_g[NW * 12];
__constant__  ull c_g[NW * 12];

__global__ void qsa_prep(const float* __restrict__ rx0,
                         const float* __restrict__ ry0,
                         const float* __restrict__ ry1) {
    int j = threadIdx.x;
    if (j < NW) {
        float cx, sx, cy, sy, cz, sz;
        sincosf(0.5f * rx0[j], &sx, &cx);
        sincosf(0.5f * ry0[j], &sy, &cy);
        sincosf(0.5f * ry1[j], &sz, &cz);
        // G = RY(ry0)@RX(rx0): a = cx*cy + i sx*sy ; b = -sy*cx - i sx*cy ;
        //                      c = sy*cx - i sx*cy ; d = cx*cy - i sx*sy
        float ar =  cx * cy, ai =  sx * sy;
        float br = -sy * cx, bi = -sx * cy;
        float cr =  sy * cx, ci = -sx * cy;
        float dr =  cx * cy, di = -sx * sy;
        ull* g = d_g + j * 8;
        g[0] = pk(ar, ar);   g[1] = pk(-ai, ai);
        g[2] = pk(br, br);   g[3] = pk(-bi, bi);
        g[4] = pk(cr, cr);   g[5] = pk(-ci, ci);
        g[6] = pk(dr, dr);   g[7] = pk(-di, di);
        ull* h = d_g + G2OFF + j * 4;
        h[0] = pk(cz, cz);   h[1] = pk(sz, sz);   h[2] = pk(-sz, -sz);
        h[3] = 0;
    }
}

// ---------- gates (coefficients from __constant__) ----------
// Complex 2x2 on register bit kb.
__device__ __forceinline__ void cgate_reg(ull* r, const int gi, const int kb) {
    const ull a2 = c_g[gi+0], ai2 = c_g[gi+1], b2 = c_g[gi+2], bi2 = c_g[gi+3];
    const ull c2 = c_g[gi+4], ci2 = c_g[gi+5], d2 = c_g[gi+6], di2 = c_g[gi+7];
#pragma unroll
    for (int m = 0; m < 8; m++) {
        if ((m >> kb) & 1) continue;
        const int m1 = m | (1 << kb);
        ull u = r[m], v = r[m1];
        ull us = swp(u), vs = swp(v);
        r[m]  = fma2(a2, u, fma2(ai2, us, fma2(b2, v, mul2(bi2, vs))));
        r[m1] = fma2(c2, u, fma2(ci2, us, fma2(d2, v, mul2(di2, vs))));
    }
}

// Complex 2x2 on lane bit lb via shuffle (coeff role select hoisted per gate).
__device__ __forceinline__ void cgate_shfl(ull* r, const int gi,
                                           const int lb, const int lane) {
    const bool hi = (lane >> lb) & 1;
    const ull p2  = hi ? c_g[gi+6] : c_g[gi+0];
    const ull pi2 = hi ? c_g[gi+7] : c_g[gi+1];
    const ull q2  = hi ? c_g[gi+4] : c_g[gi+2];
    const ull qi2 = hi ? c_g[gi+5] : c_g[gi+3];
#pragma unroll
    for (int k = 0; k < 8; k++) {
        float ux, uy; upk(r[k], ux, uy);
        float vx = __shfl_xor_sync(0xffffffffu, ux, 1 << lb);
        float vy = __shfl_xor_sync(0xffffffffu, uy, 1 << lb);
        r[k] = fma2(p2, r[k],
               fma2(pi2, pk(uy, ux),
               fma2(q2, pk(vx, vy), mul2(qi2, pk(vy, vx)))));
    }
}

// Real RY on register bit kb.
__device__ __forceinline__ void rgate_reg(ull* r, const int gi, const int kb) {
    const ull c2 = c_g[G2OFF+gi+0], s2 = c_g[G2OFF+gi+1], ns2 = c_g[G2OFF+gi+2];
#pragma unroll
    for (int m = 0; m < 8; m++) {
        if ((m >> kb) & 1) continue;
        const int m1 = m | (1 << kb);
        ull u = r[m], v = r[m1];
        r[m]  = fma2(c2, u, mul2(ns2, v));
        r[m1] = fma2(c2, v, mul2(s2, u));
    }
}

// Real RY on lane bit lb via shuffle.
__device__ __forceinline__ void rgate_shfl(ull* r, const int gi,
                                           const int lb, const int lane) {
    const bool hi = (lane >> lb) & 1;
    const ull c2 = c_g[G2OFF+gi+0];
    const ull q2 = hi ? c_g[G2OFF+gi+1] : c_g[G2OFF+gi+2];   // +s / -s
#pragma unroll
    for (int k = 0; k < 8; k++) {
        float ux, uy; upk(r[k], ux, uy);
        float vx = __shfl_xor_sync(0xffffffffu, ux, 1 << lb);
        float vy = __shfl_xor_sync(0xffffffffu, uy, 1 << lb);
        r[k] = fma2(c2, r[k], mul2(q2, pk(vx, vy)));
    }
}

__global__ __launch_bounds__(THREADS, 8)
void qsa_main(const float* __restrict__ x, float* __restrict__ out,
              const int nrows) {
    __shared__ ull   buf0[DIM];
    __shared__ ull   buf1[DIM];
    __shared__ float snorm[2][4];     // parity double-buffered per row iter
    __shared__ float swred[4 * NW];

    const int t    = threadIdx.x;
    const int lane = t & 31;
    const int w    = t >> 5;

    int par = 0;
    for (int row = blockIdx.x; row < nrows; row += gridDim.x, par ^= 1) {
        // ---- Load (layout A: i = t + 128k; lane=bits0-4, warp=bits5-6, k=bits7-9)
        ull r[8];
        float ss = 0.f;
        const float* xr = x + (size_t)row * DIM;
#pragma unroll
        for (int k = 0; k < 8; k++) {
            float v = __ldg(xr + t + THREADS * k);
            r[k] = pk(v, 0.f);
            ss += v * v;
        }
#pragma unroll
        for (int o = 16; o; o >>= 1) ss += __shfl_xor_sync(0xffffffffu, ss, o);
        if (lane == 0) snorm[par][w] = ss;   // consumed by output threads post-sync4

        // ======== Layer 1 (fused complex RY*RX per wire) ========
        cgate_reg(r, 8 * 0, 2);          // q0 <-> bit9
        cgate_reg(r, 8 * 1, 1);          // q1 <-> bit8
        cgate_reg(r, 8 * 2, 0);          // q2 <-> bit7
        cgate_shfl(r, 8 * 5, 4, lane);   // q5 <-> bit4
        cgate_shfl(r, 8 * 6, 3, lane);   // q6
        cgate_shfl(r, 8 * 7, 2, lane);   // q7
        cgate_shfl(r, 8 * 8, 1, lane);   // q8
        cgate_shfl(r, 8 * 9, 0, lane);   // q9 <-> bit0

        // ---- Exchange A -> B (layout B: i = lane | (k<<5) | (w<<8)) ----
#pragma unroll
        for (int k = 0; k < 8; k++) buf0[t + THREADS * k] = r[k];
        __syncthreads();                                   // sync1
#pragma unroll
        for (int k = 0; k < 8; k++) r[k] = buf0[lane | (k << 5) | (w << 8)];

        cgate_reg(r, 8 * 4, 0);          // q4 <-> bit5
        cgate_reg(r, 8 * 3, 1);          // q3 <-> bit6

        // ---- CNOT ring (suffix-XOR permutation), fused with exchange B -> A ----
#pragma unroll
        for (int k = 0; k < 8; k++) {
            unsigned i = (unsigned)(lane | (k << 5) | (w << 8));
            unsigned y = i;
            y ^= y >> 1; y ^= y >> 2; y ^= y >> 4; y ^= y >> 8;
            unsigned dst = (y & 0x1FFu) | (((y ^ (i >> 9)) & 1u) << 9);
            buf1[dst] = r[k];
        }
        __syncthreads();                                   // sync2
#pragma unroll
        for (int k = 0; k < 8; k++) r[k] = buf1[t + THREADS * k];

        // ======== Layer 2 (real RY per wire) ========
        rgate_reg(r, 4 * 0, 2);
        rgate_reg(r, 4 * 1, 1);
        rgate_reg(r, 4 * 2, 0);
        rgate_shfl(r, 4 * 5, 4, lane);
        rgate_shfl(r, 4 * 6, 3, lane);
        rgate_shfl(r, 4 * 7, 2, lane);
        rgate_shfl(r, 4 * 8, 1, lane);
        rgate_shfl(r, 4 * 9, 0, lane);

        // ---- Exchange A -> B again ----
#pragma unroll
        for (int k = 0; k < 8; k++) buf0[t + THREADS * k] = r[k];
        __syncthreads();                                   // sync3
#pragma unroll
        for (int k = 0; k < 8; k++) r[k] = buf0[lane | (k << 5) | (w << 8)];

        rgate_reg(r, 4 * 4, 0);          // q4 <-> bit5
        rgate_reg(r, 4 * 3, 1);          // q3 <-> bit6

        // ======== <Z_j> reduction (layout B: bits5-7 = k; 8,9 = w; 0-4 = lane) ====
        float tot = 0.f, a2 = 0.f, a3 = 0.f, a4 = 0.f;
#pragma unroll
        for (int k = 0; k < 8; k++) {
            float px, py; upk(r[k], px, py);
            float p = px * px + py * py;
            tot += p;
            a4 += (k & 1) ? -p : p;   // q4 <-> bit5
            a3 += (k & 2) ? -p : p;   // q3 <-> bit6
            a2 += (k & 4) ? -p : p;   // q2 <-> bit7
        }
        // Spawning sum/difference tree over lane bits.
        float s = tot, d4, d3, d2v, d1, d0;
        {
            float n = __shfl_xor_sync(0xffffffffu, s, 16);
            d4 = (lane & 16) ? n - s : s - n; s += n;
        }
        {
            float n = __shfl_xor_sync(0xffffffffu, s, 8);
            d3 = (lane & 8) ? n - s : s - n; s += n;
            d4 += __shfl_xor_sync(0xffffffffu, d4, 8);
        }
        {
            float n = __shfl_xor_sync(0xffffffffu, s, 4);
            d2v = (lane & 4) ? n - s : s - n; s += n;
            d4 += __shfl_xor_sync(0xffffffffu, d4, 4);
            d3 += __shfl_xor_sync(0xffffffffu, d3, 4);
        }
        {
            float n = __shfl_xor_sync(0xffffffffu, s, 2);
            d1 = (lane & 2) ? n - s : s - n; s += n;
            d4 += __shfl_xor_sync(0xffffffffu, d4, 2);
            d3 += __shfl_xor_sync(0xffffffffu, d3, 2);
            d2v += __shfl_xor_sync(0xffffffffu, d2v, 2);
        }
        {
            float n = __shfl_xor_sync(0xffffffffu, s, 1);
            d0 = (lane & 1) ? n - s : s - n; s += n;
            d4 += __shfl_xor_sync(0xffffffffu, d4, 1);
            d3 += __shfl_xor_sync(0xffffffffu, d3, 1);
            d2v += __shfl_xor_sync(0xffffffffu, d2v, 1);
            d1 += __shfl_xor_sync(0xffffffffu, d1, 1);
        }
#pragma unroll
        for (int o = 16; o; o >>= 1) {
            a2 += __shfl_xor_sync(0xffffffffu, a2, o);
            a3 += __shfl_xor_sync(0xffffffffu, a3, o);
            a4 += __shfl_xor_sync(0xffffffffu, a4, o);
        }
        if (lane == 0) {
            swred[w * NW + 0] = ((w >> 1) & 1) ? -s : s;   // q0 <-> bit9 (w bit1)
            swred[w * NW + 1] = ( w       & 1) ? -s : s;   // q1 <-> bit8
            swred[w * NW + 2] = a2;
            swred[w * NW + 3] = a3;
            swred[w * NW + 4] = a4;
            swred[w * NW + 5] = d4;
            swred[w * NW + 6] = d3;
            swred[w * NW + 7] = d2v;
            swred[w * NW + 8] = d1;
            swred[w * NW + 9] = d0;
        }
        __syncthreads();                                   // sync4
        if (t < NW) {
            float sn = snorm[par][0] + snorm[par][1] + snorm[par][2] + snorm[par][3];
            float e  = swred[t] + swred[NW + t] + swred[2 * NW + t] + swred[3 * NW + t];
            out[(size_t)row * NW + t] = e / fmaxf(sn, 1e-24f);
        }
        // next iteration's snorm writes target snorm[par^1]; swred rewrites are
        // ordered behind sync3 of the next row iteration.
    }
}

extern "C" void kernel_launch(void* const* d_in, const int* in_sizes, int n_in,
                              void* d_out, int out_size) {
    const float* x   = (const float*)d_in[0];
    const float* rx0 = (const float*)d_in[1];
    const float* ry0 = (const float*)d_in[2];
    const float* ry1 = (const float*)d_in[3];
    float* out = (float*)d_out;

    int nrows = in_sizes[0] / DIM;  // 4096

    qsa_prep<<<1, 32>>>(rx0, ry0, ry1);

    // Single merged D2D copy into __constant__ (graph-capturable).
    void* p = nullptr;
    cudaGetSymbolAddress(&p, d_g);
    cudaMemcpyToSymbolAsync(c_g, p, sizeof(ull) * NW * 12, 0,
                            cudaMemcpyDeviceToDevice, 0);

    // Persistent CTAs: 8 CTAs/SM x 148 SMs resident simultaneously.
    int grid = 1184;
    if (grid > nrows) grid = nrows;
    qsa_main<<<grid, THREADS>>>(x, out, nrows);
}